// round 3
// baseline (speedup 1.0000x reference)
#include <cuda_runtime.h>
#include <cstdint>

#define RNODES 256
#define LUTWORDS 8192        // 2^18 bits / 32
#define MSAMP 512
#define SSTEPS 512
#define NIN 32               // D*B
#define NOUT 10

// Persistent scratch (device globals — no runtime allocation allowed)
__device__ unsigned g_lutpk[RNODES * LUTWORDS];   // 8 MB bit-packed LUT
__device__ unsigned g_xbits[MSAMP * SSTEPS];      // 1 MB: 32 input bits per (m,t)
__device__ unsigned g_Wlo[64 * RNODES];           // chunk-major low bytes of primes*W
__device__ unsigned g_hib[24 * RNODES];           // [b(0..2)][w(0..7)][j] hi bitplanes
__device__ int g_is_u8;                           // bool serialization flag

// ---------------------------------------------------------------------------
// Detect whether bool tensors are serialized as 1-byte or 4-byte elements.
// ---------------------------------------------------------------------------
__global__ void k_detect(const void* xraw) {
    const unsigned char* p = (const unsigned char*)xraw;
    int t = threadIdx.x;
    int found = 0;
    for (int i = t; i < 4096; i += 256)
        if ((i & 3) && p[i]) found = 1;
    found = __syncthreads_or(found);
    if (t == 0) g_is_u8 = found ? 1 : 0;
}

// ---------------------------------------------------------------------------
// Pack the 256MB int32 0/1 LUT into 8MB of bits (fully coalesced, ballot).
// ---------------------------------------------------------------------------
__global__ void k_lutpack(const int* __restrict__ lut) {
    unsigned g = blockIdx.x * 256u + threadIdx.x;      // over 67,108,864
    unsigned v = (unsigned)lut[g] & 1u;
    unsigned m = __ballot_sync(0xffffffffu, v);
    if ((threadIdx.x & 31u) == 0u) g_lutpk[g >> 5] = m;
}

// ---------------------------------------------------------------------------
// Pack x[m, t, :] (32 bools) into one u32 per (m,t).
// ---------------------------------------------------------------------------
__global__ void k_xpack(const void* xraw) {
    unsigned g = blockIdx.x * 256u + threadIdx.x;      // over 8,388,608
    unsigned v;
    if (g_is_u8) v = ((const unsigned char*)xraw)[g] & 1u;
    else         v = (unsigned)((const int*)xraw)[g] & 1u;
    unsigned m = __ballot_sync(0xffffffffu, v);
    if ((threadIdx.x & 31u) == 0u) g_xbits[g >> 5] = m;
}

// ---------------------------------------------------------------------------
// Build weight structures. Wp[j,k] = W[j,k] ? primes[k] : 0, split as
//   lo = Wp & 255  -> chunk-major u32 (4 bytes of k per word) for dp4a
//   hi = Wp >> 8 (0..6) -> 3 bitplanes over k, 8 words of 32 bits each
// ---------------------------------------------------------------------------
__global__ void k_wprep(const void* wraw, const int* __restrict__ primes) {
    int t = blockIdx.x * 256 + threadIdx.x;            // 0..2047
    if (t >= RNODES * 8) return;
    int j = t >> 3, w = t & 7;
    unsigned lo[8] = {0, 0, 0, 0, 0, 0, 0, 0};
    unsigned hb0 = 0, hb1 = 0, hb2 = 0;
    int flag = g_is_u8;
    for (int kk = 0; kk < 32; kk++) {
        int k = w * 32 + kk;
        unsigned wv = flag ? (unsigned)(((const unsigned char*)wraw)[j * RNODES + k] & 1)
                           : ((unsigned)((const int*)wraw)[j * RNODES + k] & 1u);
        unsigned p = wv ? (unsigned)primes[k] : 0u;
        lo[kk >> 2] |= (p & 255u) << ((kk & 3) * 8);
        unsigned h = p >> 8;
        hb0 |= (h & 1u) << kk;
        hb1 |= ((h >> 1) & 1u) << kk;
        hb2 |= ((h >> 2) & 1u) << kk;
    }
    for (int cc = 0; cc < 8; cc++)
        g_Wlo[(w * 8 + cc) * RNODES + j] = lo[cc];
    g_hib[(0 * 8 + w) * RNODES + j] = hb0;
    g_hib[(1 * 8 + w) * RNODES + j] = hb1;
    g_hib[(2 * 8 + w) * RNODES + j] = hb2;
}

// ---------------------------------------------------------------------------
// Main reservoir kernel: 1 CTA per 2 samples (256 CTAs -> single wave),
// thread j = node j for both samples.
// ---------------------------------------------------------------------------
__global__ void __launch_bounds__(256, 2)
k_main(const int* __restrict__ input_nodes,
       const void* __restrict__ initraw,
       const float* __restrict__ rW,
       const float* __restrict__ rb,
       float* __restrict__ out)
{
    __shared__ unsigned s_x[2][SSTEPS];                        // 4 KB
    __shared__ __align__(16) uint4 s_r4[2][2][16];             // [buf][samp] 256B r-bytes
    __shared__ __align__(16) unsigned s_rbits[2][2][8];        // [buf][samp] r-bits

    const int m0 = blockIdx.x * 2;
    const int j = threadIdx.x;
    const int lane = j & 31, warp = j >> 5;

    // stage both samples' packed inputs
    for (int i = j; i < SSTEPS; i += 256) {
        s_x[0][i] = g_xbits[m0 * SSTEPS + i];
        s_x[1][i] = g_xbits[(m0 + 1) * SSTEPS + i];
    }

    // weights into registers (static across all 512 steps)
    unsigned Wlo[64];
#pragma unroll
    for (int c = 0; c < 64; c++) Wlo[c] = g_Wlo[c * RNODES + j];
    unsigned HB0[8], HB1[8], HB2[8];
#pragma unroll
    for (int w = 0; w < 8; w++) {
        HB0[w] = g_hib[(0 * 8 + w) * RNODES + j];
        HB1[w] = g_hib[(1 * 8 + w) * RNODES + j];
        HB2[w] = g_hib[(2 * 8 + w) * RNODES + j];
    }

    // is this node an input node, and which bit does it take?
    int isin = 0, ipos = 0;
    for (int i = 0; i < NIN; i++) {
        int n = input_nodes[i];
        if (n == j) { isin = 1; ipos = i; }
    }

    const int flag = g_is_u8;
    unsigned rinit = flag ? (unsigned)(((const unsigned char*)initraw)[j] & 1)
                          : ((unsigned)((const int*)initraw)[j] & 1u);
    unsigned r0 = rinit, r1 = rinit;

    const unsigned* lutp = g_lutpk + ((unsigned)j << 13);

    __syncthreads();   // s_x visible before loop

    int buf = 0;
    for (int t = 0; t < SSTEPS; t++) {
        // (a) input overwrite
        unsigned xw0 = s_x[0][t], xw1 = s_x[1][t];
        if (isin) { r0 = (xw0 >> ipos) & 1u; r1 = (xw1 >> ipos) & 1u; }

        // publish r (bytes for dp4a, bits for hi popcount)
        unsigned b0 = __ballot_sync(0xffffffffu, r0);
        unsigned b1 = __ballot_sync(0xffffffffu, r1);
        ((unsigned char*)s_r4[buf][0])[j] = (unsigned char)r0;
        ((unsigned char*)s_r4[buf][1])[j] = (unsigned char)r1;
        if (lane == 0) { s_rbits[buf][0][warp] = b0; s_rbits[buf][1][warp] = b1; }
        __syncthreads();

        // ---- sample 0: idx + LUT load (issue early to overlap with sample 1)
        unsigned idx0, idx1;
        {
            const uint4* q = s_r4[buf][0];
            unsigned a0 = 0, a1 = 0, a2 = 0, a3 = 0;
#pragma unroll
            for (int c = 0; c < 16; c++) {
                uint4 v = q[c];
                a0 = __dp4a(v.x, Wlo[4 * c + 0], a0);
                a1 = __dp4a(v.y, Wlo[4 * c + 1], a1);
                a2 = __dp4a(v.z, Wlo[4 * c + 2], a2);
                a3 = __dp4a(v.w, Wlo[4 * c + 3], a3);
            }
            uint4 hA = *(const uint4*)&s_rbits[buf][0][0];
            uint4 hB = *(const uint4*)&s_rbits[buf][0][4];
            unsigned rw[8] = {hA.x, hA.y, hA.z, hA.w, hB.x, hB.y, hB.z, hB.w};
            unsigned h0 = 0, h1 = 0, h2 = 0;
#pragma unroll
            for (int w = 0; w < 8; w++) {
                h0 += __popc(rw[w] & HB0[w]);
                h1 += __popc(rw[w] & HB1[w]);
                h2 += __popc(rw[w] & HB2[w]);
            }
            idx0 = (a0 + a1) + (a2 + a3) + ((h0 + 2u * h1 + 4u * h2) << 8);
        }
        unsigned wv0 = __ldg(lutp + (idx0 >> 5));

        // ---- sample 1
        {
            const uint4* q = s_r4[buf][1];
            unsigned a0 = 0, a1 = 0, a2 = 0, a3 = 0;
#pragma unroll
            for (int c = 0; c < 16; c++) {
                uint4 v = q[c];
                a0 = __dp4a(v.x, Wlo[4 * c + 0], a0);
                a1 = __dp4a(v.y, Wlo[4 * c + 1], a1);
                a2 = __dp4a(v.z, Wlo[4 * c + 2], a2);
                a3 = __dp4a(v.w, Wlo[4 * c + 3], a3);
            }
            uint4 hA = *(const uint4*)&s_rbits[buf][1][0];
            uint4 hB = *(const uint4*)&s_rbits[buf][1][4];
            unsigned rw[8] = {hA.x, hA.y, hA.z, hA.w, hB.x, hB.y, hB.z, hB.w};
            unsigned h0 = 0, h1 = 0, h2 = 0;
#pragma unroll
            for (int w = 0; w < 8; w++) {
                h0 += __popc(rw[w] & HB0[w]);
                h1 += __popc(rw[w] & HB1[w]);
                h2 += __popc(rw[w] & HB2[w]);
            }
            idx1 = (a0 + a1) + (a2 + a3) + ((h0 + 2u * h1 + 4u * h2) << 8);
        }
        unsigned wv1 = __ldg(lutp + (idx1 >> 5));

        r0 = (wv0 >> (idx0 & 31u)) & 1u;
        r1 = (wv1 >> (idx1 & 31u)) & 1u;
        buf ^= 1;
    }

    // readout: out[m, o] = sum_j rW[o, j] * rf[j] + rb[o]
    ((unsigned char*)s_r4[buf][0])[j] = (unsigned char)r0;
    ((unsigned char*)s_r4[buf][1])[j] = (unsigned char)r1;
    __syncthreads();
    if (j < NOUT) {
        const unsigned char* rf = (const unsigned char*)s_r4[buf][0];
        float acc = rb[j];
        const float* wr = rW + j * RNODES;
        for (int k = 0; k < RNODES; k++)
            acc += wr[k] * (float)rf[k];
        out[m0 * NOUT + j] = acc;
    } else if (j >= 32 && j < 32 + NOUT) {
        int o = j - 32;
        const unsigned char* rf = (const unsigned char*)s_r4[buf][1];
        float acc = rb[o];
        const float* wr = rW + o * RNODES;
        for (int k = 0; k < RNODES; k++)
            acc += wr[k] * (float)rf[k];
        out[(m0 + 1) * NOUT + o] = acc;
    }
}

// ---------------------------------------------------------------------------
// d_in order: x, input_nodes, lut, W_res, primes, init_res, readout_W, readout_b
// ---------------------------------------------------------------------------
extern "C" void kernel_launch(void* const* d_in, const int* in_sizes, int n_in,
                              void* d_out, int out_size) {
    (void)in_sizes; (void)n_in; (void)out_size;
    const void*  x       = d_in[0];
    const int*   innodes = (const int*)d_in[1];
    const int*   lut     = (const int*)d_in[2];
    const void*  wres    = d_in[3];
    const int*   primes  = (const int*)d_in[4];
    const void*  initres = d_in[5];
    const float* rW      = (const float*)d_in[6];
    const float* rb      = (const float*)d_in[7];
    float* out = (float*)d_out;

    k_detect<<<1, 256>>>(x);
    k_lutpack<<<(RNODES * LUTWORDS * 32) / 256, 256>>>(lut);   // 262144 blocks
    k_xpack<<<(MSAMP * SSTEPS * 32) / 256, 256>>>(x);          // 32768 blocks
    k_wprep<<<8, 256>>>(wres, primes);
    k_main<<<MSAMP / 2, 256>>>(innodes, initres, rW, rb, out);
}

// round 5
// speedup vs baseline: 1.3563x; 1.3563x over previous
#include <cuda_runtime.h>
#include <cstdint>

#define RNODES 256
#define LUTWORDS 8192        // 2^18 bits / 32
#define MSAMP 512
#define SSTEPS 512
#define NIN 32               // D*B
#define NOUT 10
#define SPC 4                // samples per CTA
#define NCTA (MSAMP / SPC)   // 128 -> single wave, 1 CTA per SM

// Persistent scratch (device globals — no runtime allocation allowed)
__device__ unsigned g_lutpk[RNODES * LUTWORDS];   // 8 MB bit-packed LUT
__device__ unsigned g_xbits[MSAMP * SSTEPS];      // 1 MB: 32 input bits per (m,t)
__device__ unsigned g_Wlo[64 * RNODES];           // chunk-major low bytes of primes*W
__device__ unsigned g_hib[24 * RNODES];           // [b(0..2)][w(0..7)][j] hi bitplanes
__device__ int g_is_u8;                           // bool serialization flag

// ---------------------------------------------------------------------------
// Detect whether bool tensors are serialized as 1-byte or 4-byte elements.
// ---------------------------------------------------------------------------
__global__ void k_detect(const void* xraw) {
    const unsigned char* p = (const unsigned char*)xraw;
    int t = threadIdx.x;
    int found = 0;
    for (int i = t; i < 4096; i += 256)
        if ((i & 3) && p[i]) found = 1;
    found = __syncthreads_or(found);
    if (t == 0) g_is_u8 = found ? 1 : 0;
}

// ---------------------------------------------------------------------------
// Pack the 256MB int32 0/1 LUT into 8MB of bits (fully coalesced, ballot).
// ---------------------------------------------------------------------------
__global__ void k_lutpack(const int* __restrict__ lut) {
    unsigned g = blockIdx.x * 256u + threadIdx.x;      // over 67,108,864
    unsigned v = (unsigned)lut[g] & 1u;
    unsigned m = __ballot_sync(0xffffffffu, v);
    if ((threadIdx.x & 31u) == 0u) g_lutpk[g >> 5] = m;
}

// ---------------------------------------------------------------------------
// Pack x[m, t, :] (32 bools) into one u32 per (m,t).
// ---------------------------------------------------------------------------
__global__ void k_xpack(const void* xraw) {
    unsigned g = blockIdx.x * 256u + threadIdx.x;      // over 8,388,608
    unsigned v;
    if (g_is_u8) v = ((const unsigned char*)xraw)[g] & 1u;
    else         v = (unsigned)((const int*)xraw)[g] & 1u;
    unsigned m = __ballot_sync(0xffffffffu, v);
    if ((threadIdx.x & 31u) == 0u) g_xbits[g >> 5] = m;
}

// ---------------------------------------------------------------------------
// Build weight structures. Wp[j,k] = W[j,k] ? primes[k] : 0, split as
//   lo = Wp & 255  -> chunk-major u32 (4 bytes of k per word) for dp4a
//   hi = Wp >> 8 (0..6) -> 3 bitplanes over k, 8 words of 32 bits each
// ---------------------------------------------------------------------------
__global__ void k_wprep(const void* wraw, const int* __restrict__ primes) {
    int t = blockIdx.x * 256 + threadIdx.x;            // 0..2047
    if (t >= RNODES * 8) return;
    int j = t >> 3, w = t & 7;
    unsigned lo[8] = {0, 0, 0, 0, 0, 0, 0, 0};
    unsigned hb0 = 0, hb1 = 0, hb2 = 0;
    int flag = g_is_u8;
    for (int kk = 0; kk < 32; kk++) {
        int k = w * 32 + kk;
        unsigned wv = flag ? (unsigned)(((const unsigned char*)wraw)[j * RNODES + k] & 1)
                           : ((unsigned)((const int*)wraw)[j * RNODES + k] & 1u);
        unsigned p = wv ? (unsigned)primes[k] : 0u;
        lo[kk >> 2] |= (p & 255u) << ((kk & 3) * 8);
        unsigned h = p >> 8;
        hb0 |= (h & 1u) << kk;
        hb1 |= ((h >> 1) & 1u) << kk;
        hb2 |= ((h >> 2) & 1u) << kk;
    }
    for (int cc = 0; cc < 8; cc++)
        g_Wlo[(w * 8 + cc) * RNODES + j] = lo[cc];
    g_hib[(0 * 8 + w) * RNODES + j] = hb0;
    g_hib[(1 * 8 + w) * RNODES + j] = hb1;
    g_hib[(2 * 8 + w) * RNODES + j] = hb2;
}

// ---------------------------------------------------------------------------
// Main reservoir kernel: 4 samples per CTA, 128 CTAs (1 per SM, occ 1 so the
// 255-register budget holds all weights + 4-sample state without spills).
// Thread j = node j for all 4 samples. 4 independent dp4a chains + 4
// independent LUT LDGs per thread per step give the ILP that hides latency.
// ---------------------------------------------------------------------------
__global__ void __launch_bounds__(256, 1)
k_main(const int* __restrict__ input_nodes,
       const void* __restrict__ initraw,
       const float* __restrict__ rW,
       const float* __restrict__ rb,
       float* __restrict__ out)
{
    __shared__ unsigned s_x[SPC][SSTEPS];                      // 8 KB
    __shared__ __align__(16) uint4 s_r4[2][SPC][16];           // [buf][samp] 256B r-bytes
    __shared__ __align__(16) unsigned s_rbits[2][SPC][8];      // [buf][samp] r-bits

    const int m0 = blockIdx.x * SPC;
    const int j = threadIdx.x;
    const int lane = j & 31, warp = j >> 5;

    // stage all samples' packed inputs
#pragma unroll
    for (int s = 0; s < SPC; s++)
        for (int i = j; i < SSTEPS; i += 256)
            s_x[s][i] = g_xbits[(m0 + s) * SSTEPS + i];

    // weights into registers (static across all 512 steps)
    unsigned Wlo[64];
#pragma unroll
    for (int c = 0; c < 64; c++) Wlo[c] = g_Wlo[c * RNODES + j];
    unsigned HB0[8], HB1[8], HB2[8];
#pragma unroll
    for (int w = 0; w < 8; w++) {
        HB0[w] = g_hib[(0 * 8 + w) * RNODES + j];
        HB1[w] = g_hib[(1 * 8 + w) * RNODES + j];
        HB2[w] = g_hib[(2 * 8 + w) * RNODES + j];
    }

    // is this node an input node, and which bit does it take?
    int isin = 0, ipos = 0;
    for (int i = 0; i < NIN; i++) {
        int n = input_nodes[i];
        if (n == j) { isin = 1; ipos = i; }
    }

    const int flag = g_is_u8;
    unsigned rinit = flag ? (unsigned)(((const unsigned char*)initraw)[j] & 1)
                          : ((unsigned)((const int*)initraw)[j] & 1u);
    unsigned r[SPC];
#pragma unroll
    for (int s = 0; s < SPC; s++) r[s] = rinit;

    const unsigned* lutp = g_lutpk + ((unsigned)j << 13);

    __syncthreads();   // s_x visible before loop

    int buf = 0;
    for (int t = 0; t < SSTEPS; t++) {
        // (a) input overwrite + publish r (bytes for dp4a, bits for popcount)
#pragma unroll
        for (int s = 0; s < SPC; s++) {
            unsigned xw = s_x[s][t];
            if (isin) r[s] = (xw >> ipos) & 1u;
            unsigned b = __ballot_sync(0xffffffffu, r[s]);
            ((unsigned char*)s_r4[buf][s])[j] = (unsigned char)r[s];
            if (lane == 0) s_rbits[buf][s][warp] = b;
        }
        __syncthreads();

        // (b) idx per sample, LDG issued immediately after each idx (MLP=4)
        unsigned idxv[SPC], wv[SPC];
#pragma unroll
        for (int s = 0; s < SPC; s++) {
            const uint4* q = s_r4[buf][s];
            unsigned a0 = 0, a1 = 0, a2 = 0, a3 = 0;
#pragma unroll
            for (int c = 0; c < 16; c++) {
                uint4 v = q[c];
                a0 = __dp4a(v.x, Wlo[4 * c + 0], a0);
                a1 = __dp4a(v.y, Wlo[4 * c + 1], a1);
                a2 = __dp4a(v.z, Wlo[4 * c + 2], a2);
                a3 = __dp4a(v.w, Wlo[4 * c + 3], a3);
            }
            uint4 hA = *(const uint4*)&s_rbits[buf][s][0];
            uint4 hB = *(const uint4*)&s_rbits[buf][s][4];
            unsigned rw0 = hA.x, rw1 = hA.y, rw2 = hA.z, rw3 = hA.w;
            unsigned rw4 = hB.x, rw5 = hB.y, rw6 = hB.z, rw7 = hB.w;
            unsigned h0 = __popc(rw0 & HB0[0]) + __popc(rw1 & HB0[1]) +
                          __popc(rw2 & HB0[2]) + __popc(rw3 & HB0[3]) +
                          __popc(rw4 & HB0[4]) + __popc(rw5 & HB0[5]) +
                          __popc(rw6 & HB0[6]) + __popc(rw7 & HB0[7]);
            unsigned h1 = __popc(rw0 & HB1[0]) + __popc(rw1 & HB1[1]) +
                          __popc(rw2 & HB1[2]) + __popc(rw3 & HB1[3]) +
                          __popc(rw4 & HB1[4]) + __popc(rw5 & HB1[5]) +
                          __popc(rw6 & HB1[6]) + __popc(rw7 & HB1[7]);
            unsigned h2 = __popc(rw0 & HB2[0]) + __popc(rw1 & HB2[1]) +
                          __popc(rw2 & HB2[2]) + __popc(rw3 & HB2[3]) +
                          __popc(rw4 & HB2[4]) + __popc(rw5 & HB2[5]) +
                          __popc(rw6 & HB2[6]) + __popc(rw7 & HB2[7]);
            unsigned idx = (a0 + a1) + (a2 + a3) + ((h0 + 2u * h1 + 4u * h2) << 8);
            idxv[s] = idx;
            wv[s] = __ldg(lutp + (idx >> 5));
        }

        // (c) extract next state bits
#pragma unroll
        for (int s = 0; s < SPC; s++)
            r[s] = (wv[s] >> (idxv[s] & 31u)) & 1u;

        buf ^= 1;
    }

    // readout: out[m, o] = sum_j rW[o, j] * rf[j] + rb[o]
#pragma unroll
    for (int s = 0; s < SPC; s++)
        ((unsigned char*)s_r4[buf][s])[j] = (unsigned char)r[s];
    __syncthreads();
    if (j < SPC * 16) {                        // 64 threads: sample = j/16, out = j%16
        int s = j >> 4, o = j & 15;
        if (o < NOUT) {
            const unsigned char* rf = (const unsigned char*)s_r4[buf][s];
            float acc = rb[o];
            const float* wr = rW + o * RNODES;
            for (int k = 0; k < RNODES; k++)
                acc += wr[k] * (float)rf[k];
            out[(m0 + s) * NOUT + o] = acc;
        }
    }
}

// ---------------------------------------------------------------------------
// d_in order: x, input_nodes, lut, W_res, primes, init_res, readout_W, readout_b
// ---------------------------------------------------------------------------
extern "C" void kernel_launch(void* const* d_in, const int* in_sizes, int n_in,
                              void* d_out, int out_size) {
    (void)in_sizes; (void)n_in; (void)out_size;
    const void*  x       = d_in[0];
    const int*   innodes = (const int*)d_in[1];
    const int*   lut     = (const int*)d_in[2];
    const void*  wres    = d_in[3];
    const int*   primes  = (const int*)d_in[4];
    const void*  initres = d_in[5];
    const float* rW      = (const float*)d_in[6];
    const float* rb      = (const float*)d_in[7];
    float* out = (float*)d_out;

    k_detect<<<1, 256>>>(x);
    k_lutpack<<<(RNODES * LUTWORDS * 32) / 256, 256>>>(lut);   // 262144 blocks
    k_xpack<<<(MSAMP * SSTEPS * 32) / 256, 256>>>(x);          // 32768 blocks
    k_wprep<<<8, 256>>>(wres, primes);
    k_main<<<NCTA, 256>>>(innodes, initres, rW, rb, out);
}